// round 17
// baseline (speedup 1.0000x reference)
#include <cuda_runtime.h>
#include <cuda_fp16.h>
#include <cstdint>

constexpr int NA = 1024, NB = 1024, DD = 512, KK = 256;
constexpr unsigned int GRID = 128;

// Device scratch
__device__ __half g_Xh[(NA + NB) * DD];
__device__ __half g_Fh[KK * DD];
__device__ __half g_Ph[NA * KK];
__device__ __half g_Mb[NB * KK];
__device__ unsigned int g_bar_cnt;    // monotonic, replay-safe
__device__ int g_rdyP[16];            // per 64-row Ph tile: 4 producers
__device__ int g_rdyM[16];            // per 64-row Mb tile: 4 producers
constexpr float FIXTHR = 0.25f;
constexpr int LFIXMAX = 512;

// ---------------------------------------------------------------------------
__device__ __forceinline__ uint32_t smem_u32(const void* p) {
    uint32_t r;
    asm("{ .reg .u64 t; cvta.to.shared.u64 t, %1; cvt.u32.u64 %0, t; }" : "=r"(r) : "l"(p));
    return r;
}
__device__ __forceinline__ void cp16(uint32_t dst, const void* src) {
    asm volatile("cp.async.cg.shared.global [%0], [%1], 16;" :: "r"(dst), "l"(src) : "memory");
}
__device__ __forceinline__ void cp_commit() { asm volatile("cp.async.commit_group;" ::: "memory"); }
__device__ __forceinline__ void cp_wait1()  { asm volatile("cp.async.wait_group 1;" ::: "memory"); }
__device__ __forceinline__ void cp_wait0()  { asm volatile("cp.async.wait_group 0;" ::: "memory"); }

__device__ __forceinline__ void ldm_x4(uint32_t* r, uint32_t addr) {
    asm volatile("ldmatrix.sync.aligned.m8n8.x4.shared.b16 {%0,%1,%2,%3}, [%4];"
                 : "=r"(r[0]), "=r"(r[1]), "=r"(r[2]), "=r"(r[3]) : "r"(addr));
}
__device__ __forceinline__ void mma_f16(float* d, const uint32_t* a, const uint32_t* b) {
    asm volatile(
        "mma.sync.aligned.m16n8k16.row.col.f32.f16.f16.f32 "
        "{%0,%1,%2,%3}, {%4,%5,%6,%7}, {%8,%9}, {%0,%1,%2,%3};"
        : "+f"(d[0]), "+f"(d[1]), "+f"(d[2]), "+f"(d[3])
        : "r"(a[0]), "r"(a[1]), "r"(a[2]), "r"(a[3]), "r"(b[0]), "r"(b[1]));
}

// Parametric ldmatrix addressing (stride%128==16 -> conflict-free)
__device__ __forceinline__ uint32_t a_addr(uint32_t base, int row0, int lane, int koff, uint32_t stride) {
    return base + (uint32_t)(row0 + (lane & 15)) * stride + (uint32_t)koff + ((lane >> 4) << 4);
}
__device__ __forceinline__ uint32_t b_addr(uint32_t base, int row0, int lane, int koff, uint32_t stride) {
    return base + (uint32_t)(row0 + (lane & 7) + ((lane >> 4) << 3)) * stride
                + (uint32_t)koff + (((lane >> 3) & 1) << 4);
}

// Grid barrier (128 CTAs, 1/SM, co-resident; monotonic counter, replay-safe)
__device__ __forceinline__ void grid_barrier() {
    __syncthreads();
    if (threadIdx.x == 0) {
        __threadfence();
        const unsigned int arrival = atomicAdd(&g_bar_cnt, 1u);
        const unsigned int target = (arrival / GRID + 1u) * GRID;
        unsigned int v;
        do {
            asm volatile("ld.acquire.gpu.u32 %0, [%1];" : "=r"(v) : "l"(&g_bar_cnt));
        } while (v < target);
    }
    __syncthreads();
}
__device__ __forceinline__ int ld_acq(const int* p) {
    int v;
    asm volatile("ld.acquire.gpu.s32 %0, [%1];" : "=r"(v) : "l"(p));
    return v;
}

__device__ __forceinline__ uint32_t hpack(float x, float y) {
    __half2 t = __float22half2_rn(make_float2(x, y));
    return *reinterpret_cast<uint32_t*>(&t);
}
__device__ __forceinline__ uint4 hi4(const float4& v0, const float4& v1) {
    return make_uint4(hpack(v0.x, v0.y), hpack(v0.z, v0.w),
                      hpack(v1.x, v1.y), hpack(v1.z, v1.w));
}

// smem geometry
constexpr uint32_t TSTR1 = 272;            // phase 1: 128 fp16 rows + 16B pad
constexpr uint32_t ARR1  = 64 * TSTR1;     // 17408
constexpr uint32_t S1_BUF = 2 * ARR1;      // 34816
constexpr uint32_t TSTR2 = 528;            // phase 2: 256 fp16 rows + 16B pad
constexpr uint32_t S2_PH = 0;
constexpr uint32_t S2_MB = 64 * TSTR2;     // 33792
constexpr int SMEM_DYN = 3 * S1_BUF;       // 104448

// ---------------------------------------------------------------------------
__global__ __launch_bounds__(256, 1) void fused_kernel(
    const float* __restrict__ a, const float* __restrict__ b,
    const float* __restrict__ feats, float* __restrict__ out)
{
    extern __shared__ char dsm[];
    const uint32_t sb = smem_u32(dsm);
    __shared__ int s_fixn;

    const int tid = threadIdx.x;
    const int bid = blockIdx.x;
    const int lane = tid & 31;
    const int wid = tid >> 5;
    const int gt = bid * 256 + tid;

    // =======================================================================
    // Phase 0: reset flags (bid 0) + convert hi-only.
    // =======================================================================
    if (bid == 0 && tid < 32) {
        if (tid < 16) g_rdyP[tid] = 0;
        else          g_rdyM[tid - 16] = 0;
    }
    {
#pragma unroll
        for (int k = 0; k < 2; k++) {
            const int base = (gt + k * 32768) * 8;
            const float4 v0 = *reinterpret_cast<const float4*>(a + base);
            const float4 v1 = *reinterpret_cast<const float4*>(a + base + 4);
            *reinterpret_cast<uint4*>(g_Xh + base) = hi4(v0, v1);
        }
#pragma unroll
        for (int k = 0; k < 2; k++) {
            const int base = (gt + k * 32768) * 8;
            const float4 v0 = *reinterpret_cast<const float4*>(b + base);
            const float4 v1 = *reinterpret_cast<const float4*>(b + base + 4);
            *reinterpret_cast<uint4*>(g_Xh + NA * DD + base) = hi4(v0, v1);
        }
        if (gt < 16384) {
            const int base = gt * 8;
            const float4 v0 = *reinterpret_cast<const float4*>(feats + base);
            const float4 v1 = *reinterpret_cast<const float4*>(feats + base + 4);
            *reinterpret_cast<uint4*>(g_Fh + base) = hi4(v0, v1);
        }
    }

    grid_barrier();   // ONLY grid barrier

    // =======================================================================
    // Phase 1: C = Xh · Fh^T, tile 64x64 (warp 16x32), k-chunk 128 (4 chunks),
    // 3-buffer ring, FRAGMENT DOUBLE-BUFFERED inner loop.
    // =======================================================================
    {
        const int wm = wid & 3;
        const int wn = wid >> 2;
        const int mt1 = bid >> 2;
        const int m0 = mt1 * 64;
        const int n0 = (bid & 3) * 64;
        const bool isA = (m0 < NA);

        const __half* pXh = g_Xh + (size_t)m0 * DD;
        const __half* pFh = g_Fh + (size_t)n0 * DD;

        if (tid == 0) s_fixn = 0;

        auto load_chunk = [&](int ch, uint32_t buf) {
            const int d0 = ch * 128;
#pragma unroll
            for (int u = 0; u < 4; u++) {
                const int v = tid + u * 256;
                const int r = v >> 4, s = v & 15;
                const size_t off = (size_t)r * DD + d0 + s * 8;
                const uint32_t sm = buf + (uint32_t)r * TSTR1 + (uint32_t)(s << 4);
                cp16(sm,        pXh + off);
                cp16(sm + ARR1, pFh + off);
            }
            cp_commit();
        };

        constexpr int NCH = DD / 128;   // 4
        load_chunk(0, sb);
        load_chunk(1, sb + S1_BUF);

        float acc[4][4] = {};

        for (int ch = 0; ch < NCH; ch++) {
            if (ch + 1 < NCH) cp_wait1(); else cp_wait0();
            __syncthreads();
            if (ch + 2 < NCH) load_chunk(ch + 2, sb + (uint32_t)((ch + 2) % 3) * S1_BUF);

            const uint32_t bb = sb + (uint32_t)(ch % 3) * S1_BUF;

            uint32_t ah[2][4], fh[2][2][4];
            ldm_x4(ah[0], a_addr(bb, wm * 16, lane, 0, TSTR1));
            ldm_x4(fh[0][0], b_addr(bb + ARR1, wn * 32,      lane, 0, TSTR1));
            ldm_x4(fh[0][1], b_addr(bb + ARR1, wn * 32 + 16, lane, 0, TSTR1));
#pragma unroll
            for (int ks = 0; ks < 8; ks++) {
                const int cur = ks & 1, nxt = cur ^ 1;
                if (ks + 1 < 8) {
                    const int koff = (ks + 1) * 32;
                    ldm_x4(ah[nxt], a_addr(bb, wm * 16, lane, koff, TSTR1));
                    ldm_x4(fh[nxt][0], b_addr(bb + ARR1, wn * 32,      lane, koff, TSTR1));
                    ldm_x4(fh[nxt][1], b_addr(bb + ARR1, wn * 32 + 16, lane, koff, TSTR1));
                }
#pragma unroll
                for (int nt = 0; nt < 4; nt++)
                    mma_f16(acc[nt], ah[cur], &fh[cur][nt >> 1][(nt & 1) * 2]);
            }
        }
        __syncthreads();   // ring free; reuse dsm for fixup list

        int2* fixlist = reinterpret_cast<int2*>(dsm);

#pragma unroll
        for (int nt = 0; nt < 4; nt++)
#pragma unroll
            for (int h = 0; h < 2; h++) {
                const int grow = m0 + wm * 16 + (lane >> 2) + h * 8;
                const int col  = n0 + wn * 32 + nt * 8 + (lane & 3) * 2;
                const float v0 = acc[nt][h * 2 + 0];
                const float v1 = acc[nt][h * 2 + 1];
                if (isA) {
                    const size_t idx = (size_t)grow * KK + col;
                    *reinterpret_cast<__half2*>(g_Ph + idx) =
                        __half2(__float2half(fmaxf(v0, 0.0f)), __float2half(fmaxf(v1, 0.0f)));
                } else {
                    const int br = grow - NA;
                    const size_t idx = (size_t)br * KK + col;
                    *reinterpret_cast<__half2*>(g_Mb + idx) =
                        __half2(__float2half(v0 <= 0.0f ? 1.0f : 0.0f),
                                __float2half(v1 <= 0.0f ? 1.0f : 0.0f));
                    if (fabsf(v0) < FIXTHR) {
                        const int p = atomicAdd(&s_fixn, 1);
                        if (p < LFIXMAX) fixlist[p] = make_int2(br, col);
                    }
                    if (fabsf(v1) < FIXTHR) {
                        const int p = atomicAdd(&s_fixn, 1);
                        if (p < LFIXMAX) fixlist[p] = make_int2(br, col + 1);
                    }
                }
            }
        __syncthreads();

        // Inline exact-fp32 fixup of borderline mask entries
        if (!isA) {
            int n = s_fixn;
            if (n > LFIXMAX) n = LFIXMAX;
            for (int e = wid; e < n; e += 8) {
                const int2 rc = fixlist[e];
                const float* brp = b + (size_t)rc.x * DD;
                const float* frp = feats + (size_t)rc.y * DD;
                float s = 0.0f;
#pragma unroll
                for (int i = 0; i < 16; i++) {
                    const int idx = i * 32 + lane;
                    s = fmaf(brp[idx], frp[idx], s);
                }
#pragma unroll
                for (int o = 16; o; o >>= 1)
                    s += __shfl_xor_sync(0xFFFFFFFFu, s, o);
                if (lane == 0)
                    g_Mb[(size_t)rc.x * KK + rc.y] = __float2half(s <= 0.0f ? 1.0f : 0.0f);
            }
        }
        __syncthreads();

        if (tid == 0) {
            __threadfence();
            if (isA) atomicAdd(&g_rdyP[mt1], 1);
            else     atomicAdd(&g_rdyM[mt1 - 16], 1);
        }
    }

    // =======================================================================
    // Phase 2: out = Ph · Mb^T, tile 64x128 (warp 32x32), MONOLITHIC K=256,
    // FRAGMENT DOUBLE-BUFFERED 16-step loop.
    // =======================================================================
    {
        const int it = bid >> 3;
        const int jt = (bid & 7) * 2;
        const int i0 = it * 64;
        const int j0 = (bid & 7) * 128;

        if (tid == 0) {
            while (ld_acq(&g_rdyP[it]) < 4) {}
            while (ld_acq(&g_rdyM[jt]) < 4) {}
            while (ld_acq(&g_rdyM[jt + 1]) < 4) {}
        }
        __syncthreads();

        const __half* pPh = g_Ph + (size_t)i0 * KK;
        const __half* pMb = g_Mb + (size_t)j0 * KK;

        for (int v = tid; v < 6144; v += 256) {
            if (v < 2048) {
                const int r = v >> 5, s = v & 31;
                cp16(sb + S2_PH + (uint32_t)r * TSTR2 + (uint32_t)(s << 4),
                     pPh + (size_t)r * KK + s * 8);
            } else {
                const int w = v - 2048, r = w >> 5, s = w & 31;
                cp16(sb + S2_MB + (uint32_t)r * TSTR2 + (uint32_t)(s << 4),
                     pMb + (size_t)r * KK + s * 8);
            }
        }
        cp_commit();
        cp_wait0();
        __syncthreads();

        const int wm = wid & 1;
        const int wn = wid >> 1;

        float acc[2][4][4] = {};

        uint32_t ph[2][2][4], mb[2][2][4];
        ldm_x4(ph[0][0], a_addr(sb + S2_PH, wm * 32,      lane, 0, TSTR2));
        ldm_x4(ph[0][1], a_addr(sb + S2_PH, wm * 32 + 16, lane, 0, TSTR2));
        ldm_x4(mb[0][0], b_addr(sb + S2_MB, wn * 32,      lane, 0, TSTR2));
        ldm_x4(mb[0][1], b_addr(sb + S2_MB, wn * 32 + 16, lane, 0, TSTR2));
#pragma unroll
        for (int ks = 0; ks < 16; ks++) {
            const int cur = ks & 1, nxt = cur ^ 1;
            if (ks + 1 < 16) {
                const int koff = (ks + 1) * 32;
                ldm_x4(ph[nxt][0], a_addr(sb + S2_PH, wm * 32,      lane, koff, TSTR2));
                ldm_x4(ph[nxt][1], a_addr(sb + S2_PH, wm * 32 + 16, lane, koff, TSTR2));
                ldm_x4(mb[nxt][0], b_addr(sb + S2_MB, wn * 32,      lane, koff, TSTR2));
                ldm_x4(mb[nxt][1], b_addr(sb + S2_MB, wn * 32 + 16, lane, koff, TSTR2));
            }
#pragma unroll
            for (int mt = 0; mt < 2; mt++)
#pragma unroll
                for (int nt = 0; nt < 4; nt++)
                    mma_f16(acc[mt][nt], ph[cur][mt], &mb[cur][nt >> 1][(nt & 1) * 2]);
        }

#pragma unroll
        for (int mt = 0; mt < 2; mt++)
#pragma unroll
            for (int nt = 0; nt < 4; nt++)
#pragma unroll
                for (int h = 0; h < 2; h++) {
                    const int row = i0 + wm * 32 + mt * 16 + (lane >> 2) + h * 8;
                    const int col = j0 + wn * 32 + nt * 8 + (lane & 3) * 2;
                    *reinterpret_cast<float2*>(out + (size_t)row * NB + col) =
                        make_float2(acc[mt][nt][h * 2 + 0], acc[mt][nt][h * 2 + 1]);
                }
    }
}

// ---------------------------------------------------------------------------
extern "C" void kernel_launch(void* const* d_in, const int* in_sizes, int n_in,
                              void* d_out, int out_size)
{
    const float* a     = (const float*)d_in[0];
    const float* b     = (const float*)d_in[1];
    const float* feats = (const float*)d_in[2];
    float* out = (float*)d_out;
    (void)in_sizes; (void)n_in; (void)out_size;

    cudaFuncSetAttribute(fused_kernel, cudaFuncAttributeMaxDynamicSharedMemorySize, SMEM_DYN);
    fused_kernel<<<GRID, 256, SMEM_DYN>>>(a, b, feats, out);
}